// round 3
// baseline (speedup 1.0000x reference)
#include <cuda_runtime.h>
#include <cuda_bf16.h>

// ============================================================================
// Attention_84129819394524 — fp32 baseline
//   x[4,1024,768], w_qkv[2304,768], w_proj[768,768], b_proj[768]
//   outputs: out[4,1024,768] then attn[4,12,1024,1024] (flattened, concatenated)
// Pipeline:
//   K1 qkv_kernel   : qkv = x @ w_qkv^T  -> g_q (pre-scaled), g_k, g_v  [B,H,N,Dh]
//   K2 s_kernel     : logits = q @ k^T per (b,h)  -> attn region
//   K3 softmax      : row softmax in place on attn
//   K4 o_kernel     : O = attn @ v  -> g_o in [B,N,C] layout
//   K5 proj_kernel  : out = g_o @ w_proj^T + b_proj
// All fp32, 128x128(x64) tiles, 8x8 (8x4) microtiles, smem-staged NT GEMMs.
// ============================================================================

#define NUM_HEADS 12
#define HEAD_DIM  64
#define DIMC      768
#define BATCH     4
#define SEQ       1024
#define SCALE_F   0.125f   // 64^-0.5

#define M_TOK   (BATCH * SEQ)          // 4096
#define QKV_N   (3 * DIMC)             // 2304
#define BH      (BATCH * NUM_HEADS)    // 48

#define OUT_ELEMS  ((size_t)M_TOK * DIMC)                 // 3,145,728
#define ATTN_ELEMS ((size_t)BH * SEQ * SEQ)               // 50,331,648

// ---- scratch (allocation-free: __device__ globals) ----
__device__ __align__(256) float g_q[BH * SEQ * HEAD_DIM];
__device__ __align__(256) float g_k[BH * SEQ * HEAD_DIM];
__device__ __align__(256) float g_v[BH * SEQ * HEAD_DIM];
__device__ __align__(256) float g_o[M_TOK * DIMC];
__device__ __align__(256) float g_attn[ATTN_ELEMS];   // used only if attn not in d_out
__device__ __align__(256) float g_outs[OUT_ELEMS];    // used only if out not in d_out

// ============================================================================
// K1: QKV GEMM.  C[m,n] = sum_k x[m,k] * w_qkv[n,k]   (NT)
// M=4096, N=2304, K=768.  Tiles 128x128x16, 256 threads, 8x8 micro.
// Epilogue scatters into g_q/g_k/g_v in [B,H,N,Dh]; q pre-scaled by 1/8.
// ============================================================================
#define BK   16
#define LDS_A 132   // padded row stride (floats), multiple of 4 for float4 LDS

__global__ __launch_bounds__(256)
void qkv_kernel(const float* __restrict__ A, const float* __restrict__ B)
{
    __shared__ __align__(16) float As[BK * LDS_A];
    __shared__ __align__(16) float Bs[BK * LDS_A];
    const int K = DIMC;
    const int tid = threadIdx.x;
    const int tx = tid & 15, ty = tid >> 4;
    const float* Ablk = A + (size_t)(blockIdx.y * 128) * K;
    const float* Bblk = B + (size_t)(blockIdx.x * 128) * K;

    float acc[8][8];
#pragma unroll
    for (int i = 0; i < 8; i++)
#pragma unroll
        for (int j = 0; j < 8; j++) acc[i][j] = 0.f;

    const int lrow = tid >> 2;      // 0..63
    const int lc4  = tid & 3;       // 0..3  (float4 within 16 cols)

    for (int k0 = 0; k0 < K; k0 += BK) {
#pragma unroll
        for (int half = 0; half < 2; half++) {
            int row = lrow + half * 64;
            float4 va = *(const float4*)(Ablk + (size_t)row * K + k0 + lc4 * 4);
            As[(lc4 * 4 + 0) * LDS_A + row] = va.x;
            As[(lc4 * 4 + 1) * LDS_A + row] = va.y;
            As[(lc4 * 4 + 2) * LDS_A + row] = va.z;
            As[(lc4 * 4 + 3) * LDS_A + row] = va.w;
            float4 vb = *(const float4*)(Bblk + (size_t)row * K + k0 + lc4 * 4);
            Bs[(lc4 * 4 + 0) * LDS_A + row] = vb.x;
            Bs[(lc4 * 4 + 1) * LDS_A + row] = vb.y;
            Bs[(lc4 * 4 + 2) * LDS_A + row] = vb.z;
            Bs[(lc4 * 4 + 3) * LDS_A + row] = vb.w;
        }
        __syncthreads();
#pragma unroll
        for (int kk = 0; kk < BK; kk++) {
            float af[8], bf[8];
            *(float4*)(af)     = *(const float4*)&As[kk * LDS_A + ty * 8];
            *(float4*)(af + 4) = *(const float4*)&As[kk * LDS_A + ty * 8 + 4];
            *(float4*)(bf)     = *(const float4*)&Bs[kk * LDS_A + tx * 8];
            *(float4*)(bf + 4) = *(const float4*)&Bs[kk * LDS_A + tx * 8 + 4];
#pragma unroll
            for (int i = 0; i < 8; i++)
#pragma unroll
                for (int j = 0; j < 8; j++) acc[i][j] = fmaf(af[i], bf[j], acc[i][j]);
        }
        __syncthreads();
    }

    const int m0 = blockIdx.y * 128 + ty * 8;
    const int n0 = blockIdx.x * 128 + tx * 8;
#pragma unroll
    for (int i = 0; i < 8; i++) {
        int m = m0 + i;
        int b = m >> 10, qi = m & 1023;
#pragma unroll
        for (int j = 0; j < 8; j++) {
            int n = n0 + j;
            int which = n / DIMC;
            int c = n - which * DIMC;
            int h = c >> 6, d = c & 63;
            size_t idx = (((size_t)(b * NUM_HEADS + h) * SEQ) + qi) * HEAD_DIM + d;
            float val = acc[i][j];
            if (which == 0)      g_q[idx] = val * SCALE_F;
            else if (which == 1) g_k[idx] = val;
            else                 g_v[idx] = val;
        }
    }
}

// ============================================================================
// K2: S = q @ k^T per (b,h).  M=N=1024, K=64.  Same tiling as K1 (4 k-chunks).
// ============================================================================
__global__ __launch_bounds__(256)
void s_kernel(float* attn_out)
{
    float* attn = attn_out ? attn_out : g_attn;
    __shared__ __align__(16) float As[BK * LDS_A];
    __shared__ __align__(16) float Bs[BK * LDS_A];
    const int bh = blockIdx.z;
    const int tid = threadIdx.x;
    const int tx = tid & 15, ty = tid >> 4;
    const float* Ablk = g_q + (size_t)bh * SEQ * HEAD_DIM + (size_t)(blockIdx.y * 128) * HEAD_DIM;
    const float* Bblk = g_k + (size_t)bh * SEQ * HEAD_DIM + (size_t)(blockIdx.x * 128) * HEAD_DIM;

    float acc[8][8];
#pragma unroll
    for (int i = 0; i < 8; i++)
#pragma unroll
        for (int j = 0; j < 8; j++) acc[i][j] = 0.f;

    const int lrow = tid >> 2;
    const int lc4  = tid & 3;

    for (int k0 = 0; k0 < HEAD_DIM; k0 += BK) {
#pragma unroll
        for (int half = 0; half < 2; half++) {
            int row = lrow + half * 64;
            float4 va = *(const float4*)(Ablk + (size_t)row * HEAD_DIM + k0 + lc4 * 4);
            As[(lc4 * 4 + 0) * LDS_A + row] = va.x;
            As[(lc4 * 4 + 1) * LDS_A + row] = va.y;
            As[(lc4 * 4 + 2) * LDS_A + row] = va.z;
            As[(lc4 * 4 + 3) * LDS_A + row] = va.w;
            float4 vb = *(const float4*)(Bblk + (size_t)row * HEAD_DIM + k0 + lc4 * 4);
            Bs[(lc4 * 4 + 0) * LDS_A + row] = vb.x;
            Bs[(lc4 * 4 + 1) * LDS_A + row] = vb.y;
            Bs[(lc4 * 4 + 2) * LDS_A + row] = vb.z;
            Bs[(lc4 * 4 + 3) * LDS_A + row] = vb.w;
        }
        __syncthreads();
#pragma unroll
        for (int kk = 0; kk < BK; kk++) {
            float af[8], bf[8];
            *(float4*)(af)     = *(const float4*)&As[kk * LDS_A + ty * 8];
            *(float4*)(af + 4) = *(const float4*)&As[kk * LDS_A + ty * 8 + 4];
            *(float4*)(bf)     = *(const float4*)&Bs[kk * LDS_A + tx * 8];
            *(float4*)(bf + 4) = *(const float4*)&Bs[kk * LDS_A + tx * 8 + 4];
#pragma unroll
            for (int i = 0; i < 8; i++)
#pragma unroll
                for (int j = 0; j < 8; j++) acc[i][j] = fmaf(af[i], bf[j], acc[i][j]);
        }
        __syncthreads();
    }

    const int m0 = blockIdx.y * 128 + ty * 8;
    const int n0 = blockIdx.x * 128 + tx * 8;
    float* Crow = attn + (size_t)bh * SEQ * SEQ;
#pragma unroll
    for (int i = 0; i < 8; i++) {
        float* r = Crow + (size_t)(m0 + i) * SEQ + n0;
        *(float4*)(r)     = make_float4(acc[i][0], acc[i][1], acc[i][2], acc[i][3]);
        *(float4*)(r + 4) = make_float4(acc[i][4], acc[i][5], acc[i][6], acc[i][7]);
    }
}

// ============================================================================
// K3: row softmax in place. One block (256 threads) per row of 1024.
// ============================================================================
__global__ __launch_bounds__(256)
void softmax_kernel(float* attn_out)
{
    float* attn = attn_out ? attn_out : g_attn;
    float* p = attn + (size_t)blockIdx.x * SEQ;
    const int tid = threadIdx.x;
    __shared__ float red_max[8];
    __shared__ float red_sum[8];

    float4 v = reinterpret_cast<float4*>(p)[tid];
    float m = fmaxf(fmaxf(v.x, v.y), fmaxf(v.z, v.w));
#pragma unroll
    for (int o = 16; o > 0; o >>= 1) m = fmaxf(m, __shfl_xor_sync(0xFFFFFFFFu, m, o));
    if ((tid & 31) == 0) red_max[tid >> 5] = m;
    __syncthreads();
    if (tid == 0) {
        float t = red_max[0];
#pragma unroll
        for (int i = 1; i < 8; i++) t = fmaxf(t, red_max[i]);
        red_max[0] = t;
    }
    __syncthreads();
    const float rmax = red_max[0];

    v.x = expf(v.x - rmax);
    v.y = expf(v.y - rmax);
    v.z = expf(v.z - rmax);
    v.w = expf(v.w - rmax);
    float s = v.x + v.y + v.z + v.w;
#pragma unroll
    for (int o = 16; o > 0; o >>= 1) s += __shfl_xor_sync(0xFFFFFFFFu, s, o);
    if ((tid & 31) == 0) red_sum[tid >> 5] = s;
    __syncthreads();
    if (tid == 0) {
        float t = 0.f;
#pragma unroll
        for (int i = 0; i < 8; i++) t += red_sum[i];
        red_sum[0] = t;
    }
    __syncthreads();
    const float inv = 1.0f / red_sum[0];
    v.x *= inv; v.y *= inv; v.z *= inv; v.w *= inv;
    reinterpret_cast<float4*>(p)[tid] = v;
}

// ============================================================================
// K4: O = attn @ v per (b,h).  M=1024, N=64, K=1024.  128x64x16 tiles,
// 256 threads, 8x4 micro.  Output scattered into g_o as [B,N,C].
// ============================================================================
__global__ __launch_bounds__(256)
void o_kernel(const float* attn_in)
{
    const float* attn = attn_in ? attn_in : g_attn;
    __shared__ __align__(16) float As[BK * LDS_A];   // P transposed [k][m]
    __shared__ __align__(16) float Bs[BK * HEAD_DIM];// V [k][d]
    const int bh = blockIdx.y;
    const int b = bh / NUM_HEADS, h = bh - b * NUM_HEADS;
    const int tid = threadIdx.x;
    const int tx = tid & 15, ty = tid >> 4;          // d = tx*4, m = ty*8
    const float* Pblk = attn + (size_t)bh * SEQ * SEQ + (size_t)(blockIdx.x * 128) * SEQ;
    const float* Vblk = g_v + (size_t)bh * SEQ * HEAD_DIM;

    float acc[8][4];
#pragma unroll
    for (int i = 0; i < 8; i++)
#pragma unroll
        for (int j = 0; j < 4; j++) acc[i][j] = 0.f;

    const int lrow = tid >> 2;      // P tile rows
    const int lc4  = tid & 3;
    const int vr   = tid >> 4;      // V tile row 0..15
    const int vc4  = tid & 15;      // V tile float4 col 0..15

    for (int k0 = 0; k0 < SEQ; k0 += BK) {
#pragma unroll
        for (int half = 0; half < 2; half++) {
            int row = lrow + half * 64;
            float4 va = *(const float4*)(Pblk + (size_t)row * SEQ + k0 + lc4 * 4);
            As[(lc4 * 4 + 0) * LDS_A + row] = va.x;
            As[(lc4 * 4 + 1) * LDS_A + row] = va.y;
            As[(lc4 * 4 + 2) * LDS_A + row] = va.z;
            As[(lc4 * 4 + 3) * LDS_A + row] = va.w;
        }
        {
            float4 vv = *(const float4*)(Vblk + (size_t)(k0 + vr) * HEAD_DIM + vc4 * 4);
            *(float4*)&Bs[vr * HEAD_DIM + vc4 * 4] = vv;
        }
        __syncthreads();
#pragma unroll
        for (int kk = 0; kk < BK; kk++) {
            float af[8], bf[4];
            *(float4*)(af)     = *(const float4*)&As[kk * LDS_A + ty * 8];
            *(float4*)(af + 4) = *(const float4*)&As[kk * LDS_A + ty * 8 + 4];
            *(float4*)(bf)     = *(const float4*)&Bs[kk * HEAD_DIM + tx * 4];
#pragma unroll
            for (int i = 0; i < 8; i++)
#pragma unroll
                for (int j = 0; j < 4; j++) acc[i][j] = fmaf(af[i], bf[j], acc[i][j]);
        }
        __syncthreads();
    }

    const int m0 = blockIdx.x * 128 + ty * 8;
    const int d0 = tx * 4;
#pragma unroll
    for (int i = 0; i < 8; i++) {
        size_t base = ((size_t)b * SEQ + (m0 + i)) * DIMC + h * HEAD_DIM + d0;
        *(float4*)&g_o[base] = make_float4(acc[i][0], acc[i][1], acc[i][2], acc[i][3]);
    }
}

// ============================================================================
// K5: out = g_o @ w_proj^T + b_proj.  M=4096, N=768, K=768.  Same as K1 tiling.
// ============================================================================
__global__ __launch_bounds__(256)
void proj_kernel(const float* __restrict__ B, const float* __restrict__ bias,
                 float* out_ptr)
{
    float* outp = out_ptr ? out_ptr : g_outs;
    __shared__ __align__(16) float As[BK * LDS_A];
    __shared__ __align__(16) float Bs[BK * LDS_A];
    const int K = DIMC;
    const int tid = threadIdx.x;
    const int tx = tid & 15, ty = tid >> 4;
    const float* Ablk = g_o + (size_t)(blockIdx.y * 128) * K;
    const float* Bblk = B + (size_t)(blockIdx.x * 128) * K;

    float acc[8][8];
#pragma unroll
    for (int i = 0; i < 8; i++)
#pragma unroll
        for (int j = 0; j < 8; j++) acc[i][j] = 0.f;

    const int lrow = tid >> 2;
    const int lc4  = tid & 3;

    for (int k0 = 0; k0 < K; k0 += BK) {
#pragma unroll
        for (int half = 0; half < 2; half++) {
            int row = lrow + half * 64;
            float4 va = *(const float4*)(Ablk + (size_t)row * K + k0 + lc4 * 4);
            As[(lc4 * 4 + 0) * LDS_A + row] = va.x;
            As[(lc4 * 4 + 1) * LDS_A + row] = va.y;
            As[(lc4 * 4 + 2) * LDS_A + row] = va.z;
            As[(lc4 * 4 + 3) * LDS_A + row] = va.w;
            float4 vb = *(const float4*)(Bblk + (size_t)row * K + k0 + lc4 * 4);
            Bs[(lc4 * 4 + 0) * LDS_A + row] = vb.x;
            Bs[(lc4 * 4 + 1) * LDS_A + row] = vb.y;
            Bs[(lc4 * 4 + 2) * LDS_A + row] = vb.z;
            Bs[(lc4 * 4 + 3) * LDS_A + row] = vb.w;
        }
        __syncthreads();
#pragma unroll
        for (int kk = 0; kk < BK; kk++) {
            float af[8], bf[8];
            *(float4*)(af)     = *(const float4*)&As[kk * LDS_A + ty * 8];
            *(float4*)(af + 4) = *(const float4*)&As[kk * LDS_A + ty * 8 + 4];
            *(float4*)(bf)     = *(const float4*)&Bs[kk * LDS_A + tx * 8];
            *(float4*)(bf + 4) = *(const float4*)&Bs[kk * LDS_A + tx * 8 + 4];
#pragma unroll
            for (int i = 0; i < 8; i++)
#pragma unroll
                for (int j = 0; j < 8; j++) acc[i][j] = fmaf(af[i], bf[j], acc[i][j]);
        }
        __syncthreads();
    }

    const int m0 = blockIdx.y * 128 + ty * 8;
    const int n0 = blockIdx.x * 128 + tx * 8;
#pragma unroll
    for (int i = 0; i < 8; i++) {
        float* r = outp + (size_t)(m0 + i) * DIMC + n0;
#pragma unroll
        for (int j = 0; j < 8; j++) r[j] = acc[i][j] + bias[n0 + j];
    }
}

// ============================================================================
// launch
// ============================================================================
extern "C" void kernel_launch(void* const* d_in, const int* in_sizes, int n_in,
                              void* d_out, int out_size)
{
    const float* x      = (const float*)d_in[0];
    const float* w_qkv  = (const float*)d_in[1];
    const float* w_proj = (const float*)d_in[2];
    const float* b_proj = (const float*)d_in[3];
    (void)in_sizes; (void)n_in;

    float* dof = (float*)d_out;
    float* out_ptr  = nullptr;   // nullptr -> device scratch
    float* attn_ptr = nullptr;   // nullptr -> device scratch
    size_t osz = (size_t)out_size;
    if (osz >= OUT_ELEMS + ATTN_ELEMS) { out_ptr = dof; attn_ptr = dof + OUT_ELEMS; }
    else if (osz == ATTN_ELEMS)        { attn_ptr = dof; }
    else                               { out_ptr = dof; }

    dim3 blk(256);

    // K1: QKV   grid (2304/128, 4096/128)
    qkv_kernel<<<dim3(QKV_N / 128, M_TOK / 128), blk>>>(x, w_qkv);

    // K2: S = qk^T   grid (8, 8, 48)
    s_kernel<<<dim3(SEQ / 128, SEQ / 128, BH), blk>>>(attn_ptr);

    // K3: softmax   grid (48*1024)
    softmax_kernel<<<dim3(BH * SEQ), blk>>>(attn_ptr);

    // K4: O = P@V   grid (8, 48)
    o_kernel<<<dim3(SEQ / 128, BH), blk>>>(attn_ptr);

    // K5: proj   grid (768/128, 4096/128)
    proj_kernel<<<dim3(DIMC / 128, M_TOK / 128), blk>>>(w_proj, b_proj, out_ptr);
}

// round 4
// speedup vs baseline: 2.0128x; 2.0128x over previous
#include <cuda_runtime.h>
#include <cuda_bf16.h>
#include <cstdint>

// ============================================================================
// Attention_84129819394524 — bf16-split tensor-core version
//   All GEMMs: C = A @ B^T with A[m][k], B[n][k] row-major, operands split as
//   fp32 x ≈ hi + lo (both bf16); C accumulated fp32 via 3 MMAs per tile:
//   hi*hi + hi*lo + lo*hi (error ~2^-17).
// ============================================================================

#define NUM_HEADS 12
#define HEAD_DIM  64
#define DIMC      768
#define BATCH     4
#define SEQ       1024
#define SCALE_F   0.125f

#define M_TOK   (BATCH * SEQ)          // 4096
#define QKV_N   (3 * DIMC)             // 2304
#define BH      (BATCH * NUM_HEADS)    // 48

#define OUT_ELEMS  ((size_t)M_TOK * DIMC)
#define ATTN_ELEMS ((size_t)BH * SEQ * SEQ)

// ---------------- device scratch (allocation-free) ----------------
__device__ __align__(16) __nv_bfloat16 g_xh [M_TOK * DIMC];
__device__ __align__(16) __nv_bfloat16 g_xl [M_TOK * DIMC];
__device__ __align__(16) __nv_bfloat16 g_wqh[QKV_N * DIMC];
__device__ __align__(16) __nv_bfloat16 g_wql[QKV_N * DIMC];
__device__ __align__(16) __nv_bfloat16 g_wph[DIMC * DIMC];
__device__ __align__(16) __nv_bfloat16 g_wpl[DIMC * DIMC];
__device__ __align__(16) __nv_bfloat16 g_qh [BH * SEQ * HEAD_DIM];
__device__ __align__(16) __nv_bfloat16 g_ql [BH * SEQ * HEAD_DIM];
__device__ __align__(16) __nv_bfloat16 g_kh [BH * SEQ * HEAD_DIM];
__device__ __align__(16) __nv_bfloat16 g_kl [BH * SEQ * HEAD_DIM];
__device__ __align__(16) __nv_bfloat16 g_vh [BH * SEQ * HEAD_DIM];
__device__ __align__(16) __nv_bfloat16 g_vl [BH * SEQ * HEAD_DIM];
__device__ __align__(16) __nv_bfloat16 g_vth[BH * HEAD_DIM * SEQ];
__device__ __align__(16) __nv_bfloat16 g_vtl[BH * HEAD_DIM * SEQ];
__device__ __align__(16) __nv_bfloat16 g_ph [BH * SEQ * SEQ];
__device__ __align__(16) __nv_bfloat16 g_pl [BH * SEQ * SEQ];
__device__ __align__(16) __nv_bfloat16 g_oh [M_TOK * DIMC];
__device__ __align__(16) __nv_bfloat16 g_ol [M_TOK * DIMC];
__device__ __align__(256) float g_attn[ATTN_ELEMS];  // fallback if attn not in d_out
__device__ __align__(256) float g_outs[OUT_ELEMS];   // fallback if out not in d_out

// ---------------- PTX helpers ----------------
__device__ __forceinline__ uint32_t smem_u32(const void* p) {
    return (uint32_t)__cvta_generic_to_shared(p);
}
__device__ __forceinline__ void cpasync16(uint32_t dst, const void* src) {
    asm volatile("cp.async.cg.shared.global [%0], [%1], 16;" :: "r"(dst), "l"(src));
}
__device__ __forceinline__ void ldsm_x4(uint32_t* r, uint32_t addr) {
    asm volatile("ldmatrix.sync.aligned.m8n8.x4.shared.b16 {%0,%1,%2,%3}, [%4];"
                 : "=r"(r[0]), "=r"(r[1]), "=r"(r[2]), "=r"(r[3]) : "r"(addr));
}
__device__ __forceinline__ void mma16816(float* c, const uint32_t* a, const uint32_t* b) {
    asm volatile("mma.sync.aligned.m16n8k16.row.col.f32.bf16.bf16.f32 "
                 "{%0,%1,%2,%3}, {%4,%5,%6,%7}, {%8,%9}, {%0,%1,%2,%3};"
                 : "+f"(c[0]), "+f"(c[1]), "+f"(c[2]), "+f"(c[3])
                 : "r"(a[0]), "r"(a[1]), "r"(a[2]), "r"(a[3]), "r"(b[0]), "r"(b[1]));
}
__device__ __forceinline__ void split2(float v, __nv_bfloat16& h, __nv_bfloat16& l) {
    h = __float2bfloat16_rn(v);
    l = __float2bfloat16_rn(v - __bfloat162float(h));
}

// ============================================================================
// Generic mainloop: block computes 128 x BN tile of C = A @ B^T, K multiple
// of 32.  A,B row-major bf16 (hi/lo).  256 threads, warps 4(m) x 2(n).
// Double-buffered cp.async smem, padded stride 40 halfs.
// ============================================================================
#define SPAD 40

template<int BN>
__device__ __forceinline__ void gemm_tile(
    const __nv_bfloat16* __restrict__ Agh, const __nv_bfloat16* __restrict__ Agl, int lda,
    const __nv_bfloat16* __restrict__ Bgh, const __nv_bfloat16* __restrict__ Bgl, int ldb,
    int K, float (&acc)[2][BN / 16][4])
{
    extern __shared__ char smem_raw[];
    constexpr int NT   = BN / 16;       // n8-tiles per warp
    constexpr int ASZ  = 128 * SPAD * 2;
    constexpr int BSZ  = BN  * SPAD * 2;
    constexpr int STAGE = 2 * ASZ + 2 * BSZ;

    const int tid  = threadIdx.x;
    const int lane = tid & 31;
    const int warp = tid >> 5;
    const int wm = (warp >> 1) * 32;
    const int wn = (warp & 1) * (BN / 2);

    const int lc = tid & 3;        // 16B chunk within 32-half row
    const int lr = tid >> 2;       // row 0..63

    const uint32_t sbase = smem_u32(smem_raw);

    auto load_stage = [&](int s, int k0) {
        uint32_t base = sbase + s * STAGE;
#pragma unroll
        for (int rr = 0; rr < 2; rr++) {
            int row = lr + rr * 64;
            uint32_t doff = (uint32_t)(row * SPAD + lc * 8) * 2;
            const __nv_bfloat16* sa = Agh + (size_t)row * lda + k0 + lc * 8;
            const __nv_bfloat16* sl = Agl + (size_t)row * lda + k0 + lc * 8;
            cpasync16(base + doff, sa);
            cpasync16(base + ASZ + doff, sl);
        }
#pragma unroll
        for (int rr = 0; rr < BN / 64; rr++) {
            int row = lr + rr * 64;
            uint32_t doff = (uint32_t)(row * SPAD + lc * 8) * 2;
            const __nv_bfloat16* sb_ = Bgh + (size_t)row * ldb + k0 + lc * 8;
            const __nv_bfloat16* sl = Bgl + (size_t)row * ldb + k0 + lc * 8;
            cpasync16(base + 2 * ASZ + doff, sb_);
            cpasync16(base + 2 * ASZ + BSZ + doff, sl);
        }
    };

    const int a_row = wm + (lane & 15);
    const int a_co  = (lane >> 4) << 3;
    const int g     = lane >> 3;
    const int b_rowbase = wn + (g >> 1) * 8 + (lane & 7);
    const int b_co  = (g & 1) * 8;

    int niter = K >> 5;
    load_stage(0, 0);
    asm volatile("cp.async.commit_group;");

    for (int it = 0; it < niter; it++) {
        int buf = it & 1;
        if (it + 1 < niter) {
            load_stage(buf ^ 1, (it + 1) * 32);
            asm volatile("cp.async.commit_group;");
            asm volatile("cp.async.wait_group 1;");
        } else {
            asm volatile("cp.async.wait_group 0;");
        }
        __syncthreads();

        uint32_t sb = sbase + buf * STAGE;
#pragma unroll
        for (int k16 = 0; k16 < 32; k16 += 16) {
            uint32_t ah[2][4], al[2][4];
#pragma unroll
            for (int mt = 0; mt < 2; mt++) {
                uint32_t addr = sb + (uint32_t)(((a_row + mt * 16) * SPAD + k16 + a_co) * 2);
                ldsm_x4(ah[mt], addr);
                ldsm_x4(al[mt], addr + ASZ);
            }
            uint32_t bhf[NT][2], blf[NT][2];
#pragma unroll
            for (int u = 0; u < NT; u += 2) {
                uint32_t addr = sb + 2 * ASZ +
                    (uint32_t)(((b_rowbase + u * 8) * SPAD + k16 + b_co) * 2);
                uint32_t t[4];
                ldsm_x4(t, addr);
                bhf[u][0] = t[0]; bhf[u][1] = t[1];
                bhf[u + 1][0] = t[2]; bhf[u + 1][1] = t[3];
                ldsm_x4(t, addr + BSZ);
                blf[u][0] = t[0]; blf[u][1] = t[1];
                blf[u + 1][0] = t[2]; blf[u + 1][1] = t[3];
            }
#pragma unroll
            for (int mt = 0; mt < 2; mt++) {
#pragma unroll
                for (int u = 0; u < NT; u++) {
                    mma16816(acc[mt][u], ah[mt], bhf[u]);
                    mma16816(acc[mt][u], ah[mt], blf[u]);
                    mma16816(acc[mt][u], al[mt], bhf[u]);
                }
            }
        }
        __syncthreads();
    }
}

// ============================================================================
// split kernels: fp32 -> (hi, lo) bf16
// ============================================================================
__global__ __launch_bounds__(256)
void split_kernel(const float4* __restrict__ src, __nv_bfloat162* __restrict__ hi,
                  __nv_bfloat162* __restrict__ lo, int n4)
{
    int i = blockIdx.x * blockDim.x + threadIdx.x;
    if (i >= n4) return;
    float4 v = src[i];
    __nv_bfloat16 h0, h1, h2, h3, l0, l1, l2, l3;
    split2(v.x, h0, l0); split2(v.y, h1, l1);
    split2(v.z, h2, l2); split2(v.w, h3, l3);
    hi[2 * i]     = __nv_bfloat162(h0, h1);
    hi[2 * i + 1] = __nv_bfloat162(h2, h3);
    lo[2 * i]     = __nv_bfloat162(l0, l1);
    lo[2 * i + 1] = __nv_bfloat162(l2, l3);
}

// ============================================================================
// K1: QKV GEMM. C[4096][2304] = xs @ wqkvs^T. Epilogue scatters q/k/v hi/lo.
// ============================================================================
__global__ __launch_bounds__(256)
void qkv_mma()
{
    float acc[2][8][4];
#pragma unroll
    for (int a = 0; a < 2; a++)
#pragma unroll
        for (int b = 0; b < 8; b++)
#pragma unroll
            for (int c = 0; c < 4; c++) acc[a][b][c] = 0.f;

    const int bx = blockIdx.x, by = blockIdx.y;
    gemm_tile<128>(g_xh + (size_t)(by * 128) * DIMC, g_xl + (size_t)(by * 128) * DIMC, DIMC,
                   g_wqh + (size_t)(bx * 128) * DIMC, g_wql + (size_t)(bx * 128) * DIMC, DIMC,
                   DIMC, acc);

    const int lane = threadIdx.x & 31, warp = threadIdx.x >> 5;
    const int wm = (warp >> 1) * 32, wn = (warp & 1) * 64;
    const int r = lane >> 2, cc = (lane & 3) * 2;

    const int which = bx / 6;           // 0:q 1:k 2:v (768 % 128 == 0)
    __nv_bfloat16 *dh, *dl;
    float scl = 1.f;
    if (which == 0)      { dh = g_qh; dl = g_ql; scl = SCALE_F; }
    else if (which == 1) { dh = g_kh; dl = g_kl; }
    else                 { dh = g_vh; dl = g_vl; }
    const int cbase = bx * 128 - which * DIMC;

#pragma unroll
    for (int mt = 0; mt < 2; mt++) {
#pragma unroll
        for (int nt = 0; nt < 8; nt++) {
            int c = cbase + wn + nt * 8 + cc;
            int h = c >> 6, d = c & 63;
#pragma unroll
            for (int half = 0; half < 2; half++) {
                int m = by * 128 + wm + mt * 16 + r + half * 8;
                int b = m >> 10, qi = m & 1023;
                size_t idx = ((size_t)((b * NUM_HEADS + h) * SEQ + qi)) * HEAD_DIM + d;
                float v0 = acc[mt][nt][half * 2]     * scl;
                float v1 = acc[mt][nt][half * 2 + 1] * scl;
                __nv_bfloat16 h0, h1, l0, l1;
                split2(v0, h0, l0); split2(v1, h1, l1);
                *(__nv_bfloat162*)&dh[idx] = __nv_bfloat162(h0, h1);
                *(__nv_bfloat162*)&dl[idx] = __nv_bfloat162(l0, l1);
            }
        }
    }
}

// ============================================================================
// K2: transpose v [bh][seq][64] -> vt [bh][64][seq]  (hi and lo)
// ============================================================================
__global__ __launch_bounds__(256)
void vt_kernel()
{
    __shared__ __nv_bfloat16 tile[32][33];
    const int bh = blockIdx.z, bx = blockIdx.x, by = blockIdx.y;
    const int tx = threadIdx.x, ty = threadIdx.y;
#pragma unroll
    for (int which = 0; which < 2; which++) {
        const __nv_bfloat16* src = (which ? g_vl : g_vh) + (size_t)bh * SEQ * HEAD_DIM;
        __nv_bfloat16* dst = (which ? g_vtl : g_vth) + (size_t)bh * HEAD_DIM * SEQ;
#pragma unroll
        for (int j = 0; j < 4; j++) {
            int s = bx * 32 + ty + j * 8;
            tile[ty + j * 8][tx] = src[(size_t)s * HEAD_DIM + by * 32 + tx];
        }
        __syncthreads();
#pragma unroll
        for (int j = 0; j < 4; j++) {
            int d = by * 32 + ty + j * 8;
            dst[(size_t)d * SEQ + bx * 32 + tx] = tile[tx][ty + j * 8];
        }
        __syncthreads();
    }
}

// ============================================================================
// K3: S = q @ k^T per (b,h).  fp32 logits -> attn buffer.
// ============================================================================
__global__ __launch_bounds__(256)
void s_mma(float* attn_out)
{
    float* attn = attn_out ? attn_out : g_attn;
    float acc[2][8][4];
#pragma unroll
    for (int a = 0; a < 2; a++)
#pragma unroll
        for (int b = 0; b < 8; b++)
#pragma unroll
            for (int c = 0; c < 4; c++) acc[a][b][c] = 0.f;

    const int bh = blockIdx.z, bx = blockIdx.x, by = blockIdx.y;
    const size_t hb = (size_t)bh * SEQ * HEAD_DIM;
    gemm_tile<128>(g_qh + hb + (size_t)(by * 128) * HEAD_DIM,
                   g_ql + hb + (size_t)(by * 128) * HEAD_DIM, HEAD_DIM,
                   g_kh + hb + (size_t)(bx * 128) * HEAD_DIM,
                   g_kl + hb + (size_t)(bx * 128) * HEAD_DIM, HEAD_DIM,
                   HEAD_DIM, acc);

    const int lane = threadIdx.x & 31, warp = threadIdx.x >> 5;
    const int wm = (warp >> 1) * 32, wn = (warp & 1) * 64;
    const int r = lane >> 2, cc = (lane & 3) * 2;
    float* C = attn + (size_t)bh * SEQ * SEQ;

#pragma unroll
    for (int mt = 0; mt < 2; mt++) {
#pragma unroll
        for (int nt = 0; nt < 8; nt++) {
            int n = bx * 128 + wn + nt * 8 + cc;
#pragma unroll
            for (int half = 0; half < 2; half++) {
                int m = by * 128 + wm + mt * 16 + r + half * 8;
                *(float2*)&C[(size_t)m * SEQ + n] =
                    make_float2(acc[mt][nt][half * 2], acc[mt][nt][half * 2 + 1]);
            }
        }
    }
}

// ============================================================================
// K4: row softmax in place + emit P hi/lo bf16
// ============================================================================
__global__ __launch_bounds__(256)
void softmax_kernel(float* attn_out)
{
    float* attn = attn_out ? attn_out : g_attn;
    float* p = attn + (size_t)blockIdx.x * SEQ;
    const size_t pbase = (size_t)blockIdx.x * SEQ;
    const int tid = threadIdx.x;
    __shared__ float red_max[8];
    __shared__ float red_sum[8];

    float4 v = reinterpret_cast<float4*>(p)[tid];
    float m = fmaxf(fmaxf(v.x, v.y), fmaxf(v.z, v.w));
#pragma unroll
    for (int o = 16; o > 0; o >>= 1) m = fmaxf(m, __shfl_xor_sync(0xFFFFFFFFu, m, o));
    if ((tid & 31) == 0) red_max[tid >> 5] = m;
    __syncthreads();
    if (tid == 0) {
        float t = red_max[0];
#pragma unroll
        for (int i = 1; i < 8; i++) t = fmaxf(t, red_max[i]);
        red_max[0] = t;
    }
    __syncthreads();
    const float rmax = red_max[0];

    v.x = expf(v.x - rmax); v.y = expf(v.y - rmax);
    v.z = expf(v.z - rmax); v.w = expf(v.w - rmax);
    float s = v.x + v.y + v.z + v.w;
#pragma unroll
    for (int o = 16; o > 0; o >>= 1) s += __shfl_xor_sync(0xFFFFFFFFu, s, o);
    if ((tid & 31) == 0) red_sum[tid >> 5] = s;
    __syncthreads();
    if (tid == 0) {
        float t = 0.f;
#pragma unroll
        for (int i = 0; i < 8; i++) t += red_sum[i];
        red_sum[0] = t;
    }
    __syncthreads();
    const float inv = 1.0f / red_sum[0];
    v.x *= inv; v.y *= inv; v.z *= inv; v.w *= inv;
    reinterpret_cast<float4*>(p)[tid] = v;

    __nv_bfloat16 h0, h1, h2, h3, l0, l1, l2, l3;
    split2(v.x, h0, l0); split2(v.y, h1, l1);
    split2(v.z, h2, l2); split2(v.w, h3, l3);
    size_t idx = pbase + tid * 4;
    *(__nv_bfloat162*)&g_ph[idx]     = __nv_bfloat162(h0, h1);
    *(__nv_bfloat162*)&g_ph[idx + 2] = __nv_bfloat162(h2, h3);
    *(__nv_bfloat162*)&g_pl[idx]     = __nv_bfloat162(l0, l1);
    *(__nv_bfloat162*)&g_pl[idx + 2] = __nv_bfloat162(l2, l3);
}

// ============================================================================
// K5: O = P @ vt^T per (b,h).  [1024][64], K=1024.  Epilogue -> O hi/lo [B,N,C]
// ============================================================================
__global__ __launch_bounds__(256)
void o_mma()
{
    float acc[2][4][4];
#pragma unroll
    for (int a = 0; a < 2; a++)
#pragma unroll
        for (int b = 0; b < 4; b++)
#pragma unroll
            for (int c = 0; c < 4; c++) acc[a][b][c] = 0.f;

    const int bh = blockIdx.y, bx = blockIdx.x;
    const int b = bh / NUM_HEADS, h = bh - b * NUM_HEADS;
    gemm_tile<64>(g_ph + (size_t)bh * SEQ * SEQ + (size_t)(bx * 128) * SEQ,
                  g_pl + (size_t)bh * SEQ * SEQ + (size_t)(bx * 128) * SEQ, SEQ,
                  g_vth + (size_t)bh * HEAD_DIM * SEQ,
                  g_vtl + (size_t)bh * HEAD_DIM * SEQ, SEQ,
                  SEQ, acc);

    const int lane = threadIdx.x & 31, warp = threadIdx.x >> 5;
    const int wm = (warp >> 1) * 32, wn = (warp & 1) * 32;
    const int r = lane >> 2, cc = (lane & 3) * 2;

#pragma unroll
    for (int mt = 0; mt < 2; mt++) {
#pragma unroll
        for (int nt = 0; nt < 4; nt++) {
            int d = wn + nt * 8 + cc;
#pragma unroll
            for (int half = 0; half < 2; half++) {
                int mseq = bx * 128 + wm + mt * 16 + r + half * 8;
                size_t idx = ((size_t)b * SEQ + mseq) * DIMC + h * HEAD_DIM + d;
                float v0 = acc[mt][nt][half * 2];
                float v1 = acc[mt][nt][half * 2 + 1];
                __nv_bfloat16 h0, h1, l0, l1;
                split2(v0, h0, l0); split2(v1, h1, l1);
                *(__nv_bfloat162*)&g_oh[idx] = __nv_bfloat162(h0, h1);
                *(__nv_bfloat162*)&g_ol[idx] = __nv_bfloat162(l0, l1);
            }
        }
    }
}

// ============================================================================
// K6: out = O @ w_proj^T + bias  [4096][768], K=768, fp32 out.
// ============================================================================
__global__ __launch_bounds__(256)
void proj_mma(const float* __restrict__ bias, float* out_ptr)
{
    float* outp = out_ptr ? out_ptr : g_outs;
    float acc[2][8][4];
#pragma unroll
    for (int a = 0; a < 2; a++)
#pragma unroll
        for (int b = 0; b < 8; b++)
#pragma unroll
            for (int c = 0; c < 4; c++) acc[a][b][c] = 0.f;

    const int bx = blockIdx.x, by = blockIdx.y;
    gemm_tile<128>(g_oh + (size_t)(by * 128) * DIMC, g_ol + (size_t)(by * 128) * DIMC, DIMC,
                   g_wph + (size_t)(bx * 128) * DIMC, g_wpl + (size_t)(bx * 128) * DIMC, DIMC,
                   DIMC, acc);

    const int lane = threadIdx.x & 31, warp = threadIdx.x >> 5;
    const int wm = (warp >> 1) * 32, wn = (warp & 1) * 64;
    const int r = lane >> 2, cc = (lane & 3) * 2;

#pragma unroll
    for (int mt = 0; mt < 2; mt++) {
#pragma unroll
        for (int nt = 0; nt < 8; nt++) {
            int n = bx * 128 + wn + nt * 8 + cc;
            float b0 = bias[n], b1 = bias[n + 1];
#pragma unroll
            for (int half = 0; half < 2; half++) {
                int m = by * 128 + wm + mt * 16 + r + half * 8;
                *(float2*)&outp[(size_t)m * DIMC + n] =
                    make_float2(acc[mt][nt][half * 2] + b0, acc[mt][nt][half * 2 + 1] + b1);
            }
        }
    }
}

// ============================================================================
// launch
// ============================================================================
extern "C" void kernel_launch(void* const* d_in, const int* in_sizes, int n_in,
                              void* d_out, int out_size)
{
    const float* x      = (const float*)d_in[0];
    const float* w_qkv  = (const float*)d_in[1];
    const float* w_proj = (const float*)d_in[2];
    const float* b_proj = (const float*)d_in[3];
    (void)in_sizes; (void)n_in;

    float* dof = (float*)d_out;
    float* out_ptr  = nullptr;
    float* attn_ptr = nullptr;
    size_t osz = (size_t)out_size;
    if (osz >= OUT_ELEMS + ATTN_ELEMS) { out_ptr = dof; attn_ptr = dof + OUT_ELEMS; }
    else if (osz == ATTN_ELEMS)        { attn_ptr = dof; }
    else                               { out_ptr = dof; }

    const int SMEM_BIG = 2 * (2 * 128 * SPAD * 2 + 2 * 128 * SPAD * 2);  // 81920
    const int SMEM_O   = 2 * (2 * 128 * SPAD * 2 + 2 * 64  * SPAD * 2);  // 61440
    cudaFuncSetAttribute(qkv_mma,  cudaFuncAttributeMaxDynamicSharedMemorySize, SMEM_BIG);
    cudaFuncSetAttribute(s_mma,    cudaFuncAttributeMaxDynamicSharedMemorySize, SMEM_BIG);
    cudaFuncSetAttribute(proj_mma, cudaFuncAttributeMaxDynamicSharedMemorySize, SMEM_BIG);
    cudaFuncSetAttribute(o_mma,    cudaFuncAttributeMaxDynamicSharedMemorySize, SMEM_O);

    void *p_xh, *p_xl, *p_wqh, *p_wql, *p_wph, *p_wpl;
    cudaGetSymbolAddress(&p_xh, g_xh);   cudaGetSymbolAddress(&p_xl, g_xl);
    cudaGetSymbolAddress(&p_wqh, g_wqh); cudaGetSymbolAddress(&p_wql, g_wql);
    cudaGetSymbolAddress(&p_wph, g_wph); cudaGetSymbolAddress(&p_wpl, g_wpl);

    dim3 blk(256);

    // splits
    {
        int n4 = M_TOK * DIMC / 4;
        split_kernel<<<(n4 + 255) / 256, blk>>>((const float4*)x,
            (__nv_bfloat162*)p_xh, (__nv_bfloat162*)p_xl, n4);
    }
    {
        int n4 = QKV_N * DIMC / 4;
        split_kernel<<<(n4 + 255) / 256, blk>>>((const float4*)w_qkv,
            (__nv_bfloat162*)p_wqh, (__nv_bfloat162*)p_wql, n4);
    }
    {
        int n4 = DIMC * DIMC / 4;
        split_kernel<<<(n4 + 255) / 256, blk>>>((const float4*)w_proj,
            (__nv_bfloat162*)p_wph, (__nv_bfloat162*)p_wpl, n4);
    }

    // QKV GEMM
    qkv_mma<<<dim3(QKV_N / 128, M_TOK / 128), blk, SMEM_BIG>>>();

    // V transpose
    vt_kernel<<<dim3(SEQ / 32, HEAD_DIM / 32, BH), dim3(32, 8)>>>();

    // S = q k^T
    s_mma<<<dim3(SEQ / 128, SEQ / 128, BH), blk, SMEM_BIG>>>(attn_ptr);

    // softmax (+ P split)
    softmax_kernel<<<dim3(BH * SEQ), blk>>>(attn_ptr);

    // O = P V
    o_mma<<<dim3(SEQ / 128, BH), blk, SMEM_O>>>();

    // proj
    proj_mma<<<dim3(DIMC / 128, M_TOK / 128), blk, SMEM_BIG>>>(b_proj, out_ptr);
}